// round 16
// baseline (speedup 1.0000x reference)
#include <cuda_runtime.h>
#include <math.h>

// ----------------------------------------------------------------------------
// Problem constants (fixed shapes)
// ----------------------------------------------------------------------------
#define T_STEPS 4096
#define INP_DIM 512
#define HID     1024
#define GATES   4096   // 4*HID

// Recurrent kernel config
#define NCTA      128           // CTAs; each owns 8 hidden columns
#define COLS      8             // columns per CTA
#define NTHREADS  256           // 8 warps; warp w owns column j0+w

// SMEM layout (floats):
#define SW1_F     (2 * 8 * 1024)
#define SCR_F     (8 * 1024)
#define SMEM_FLOATS (SW1_F + SCR_F + 1024 + 1024)
#define SMEM_BYTES  (SMEM_FLOATS * 4)

// Poll pacing (dependent-FMA units; ~4 cyc each)
#define PACE_STEADY 44   // ~176 cyc (best-measured family)

// ----------------------------------------------------------------------------
// Device scratch (allocation-free: __device__ globals)
// ----------------------------------------------------------------------------
__device__ float g_xp[(size_t)T_STEPS * GATES];   // 64 MB: x @ W_xg
// Exchange arrays: fp32 values with the step-parity tag packed into mantissa
// bit 0 (the gather is a full barrier => 1-bit tag suffices; (t+1)&1 avoids
// colliding with the zero-initialized state).
__device__ unsigned g_cpack[HID];
__device__ unsigned g_hpack[HID];

// ----------------------------------------------------------------------------
// Kernel 1: x_proj = x @ W_xg   (fp32 SGEMM, 128x128 tile, BK=16, 8x8/thread)
// ----------------------------------------------------------------------------
#define BSP 132   // padded SMEM row

__global__ void __launch_bounds__(256)
sgemm_xproj(const float* __restrict__ A,   // x      [4096, 512]
            const float* __restrict__ B)   // W_xg   [512, 4096]
{
    __shared__ float As[16 * BSP];
    __shared__ float Bs[16 * BSP];

    const int tid = threadIdx.x;
    const int bm  = blockIdx.y;
    const int bn  = blockIdx.x;
    const int ty  = tid >> 4;
    const int tx  = tid & 15;

    float acc[8][8];
#pragma unroll
    for (int i = 0; i < 8; i++)
#pragma unroll
        for (int j = 0; j < 8; j++) acc[i][j] = 0.f;

    for (int kt = 0; kt < INP_DIM / 16; kt++) {
#pragma unroll
        for (int s = 0; s < 2; s++) {
            int f   = tid + s * 256;
            int row = f >> 2;
            int kq  = f & 3;
            float4 av = *(const float4*)(A + (size_t)(bm * 128 + row) * INP_DIM
                                           + kt * 16 + kq * 4);
            As[(kq * 4 + 0) * BSP + row] = av.x;
            As[(kq * 4 + 1) * BSP + row] = av.y;
            As[(kq * 4 + 2) * BSP + row] = av.z;
            As[(kq * 4 + 3) * BSP + row] = av.w;
        }
#pragma unroll
        for (int s = 0; s < 2; s++) {
            int f  = tid + s * 256;
            int kk = f >> 5;
            int cq = f & 31;
            float4 bv = *(const float4*)(B + (size_t)(kt * 16 + kk) * GATES
                                           + bn * 128 + cq * 4);
            *(float4*)(&Bs[kk * BSP + cq * 4]) = bv;
        }
        __syncthreads();

#pragma unroll
        for (int kk = 0; kk < 16; kk++) {
            float4 a0 = *(const float4*)(&As[kk * BSP + ty * 8]);
            float4 a1 = *(const float4*)(&As[kk * BSP + ty * 8 + 4]);
            float4 b0 = *(const float4*)(&Bs[kk * BSP + tx * 8]);
            float4 b1 = *(const float4*)(&Bs[kk * BSP + tx * 8 + 4]);
            float ar[8] = {a0.x, a0.y, a0.z, a0.w, a1.x, a1.y, a1.z, a1.w};
            float br[8] = {b0.x, b0.y, b0.z, b0.w, b1.x, b1.y, b1.z, b1.w};
#pragma unroll
            for (int i = 0; i < 8; i++)
#pragma unroll
                for (int j = 0; j < 8; j++) acc[i][j] += ar[i] * br[j];
        }
        __syncthreads();
    }

#pragma unroll
    for (int i = 0; i < 8; i++) {
        size_t base = (size_t)(bm * 128 + ty * 8 + i) * GATES + bn * 128 + tx * 8;
        *(float4*)(&g_xp[base])     = make_float4(acc[i][0], acc[i][1], acc[i][2], acc[i][3]);
        *(float4*)(&g_xp[base + 4]) = make_float4(acc[i][4], acc[i][5], acc[i][6], acc[i][7]);
    }
}

// ----------------------------------------------------------------------------
// Fast pointwise (fp32, ~1e-6 rel err)
// ----------------------------------------------------------------------------
__device__ __forceinline__ float fsigmoid(float x) {
    return 1.0f / (1.0f + __expf(-x));
}
__device__ __forceinline__ float ftanh(float x) {
    return 1.0f - 2.0f / (__expf(2.0f * x) + 1.0f);
}

// ----------------------------------------------------------------------------
// Mantissa-tagged broadcast. Producer: one volatile 4B store of the fp32
// value with mantissa bit0 = (t+1)&1 (rel. perturbation 2^-24). Consumer:
// thread tid polls its 4 contiguous columns with ONE ld.volatile.v4.u32
// (16B, single 32B sector) until all four tag bits match.
// ----------------------------------------------------------------------------
__device__ __forceinline__ void publish(unsigned* arr, int j,
                                        unsigned tagbit, float v) {
    unsigned b = (__float_as_uint(v) & ~1u) | tagbit;
    *((volatile unsigned*)(arr + j)) = b;
}

__device__ __forceinline__ void pace_fmas(int n, float* sink) {
    float s = *sink;
    for (int i = 0; i < n; i++)
        asm volatile("fma.rn.f32 %0, %0, %1, %2;"
                     : "+f"(s) : "f"(0.5f), "f"(0.25f));
    *sink = s;
}

// Gathers into dst (smem) AND returns this thread's 4 values
// (used for the coalesced `out` store on the h-exchange).
__device__ __forceinline__ float4 poll_gather4(const unsigned* arr,
                                               unsigned tagbit, float* dst,
                                               int tid, int pace, float* sink) {
    const unsigned* p = arr + 4 * tid;
    unsigned x, y, z, u;
    for (;;) {
        asm volatile("ld.volatile.global.v4.u32 {%0,%1,%2,%3},[%4];"
                     : "=r"(x), "=r"(y), "=r"(z), "=r"(u) : "l"(p) : "memory");
        unsigned m = tagbit ? (x & y & z & u) : ~(x | y | z | u);
        if (m & 1u) break;
        pace_fmas(pace, sink);
    }
    float4 v = make_float4(__uint_as_float(x), __uint_as_float(y),
                           __uint_as_float(z), __uint_as_float(u));
    *(float4*)(dst + 4 * tid) = v;
    return v;
}

// ----------------------------------------------------------------------------
// Kernel 2: persistent recurrence. 128 CTAs x 256 threads; warp w owns
// column j = 8*blockIdx.x + w.
// RESIDENCY BY CRITICALITY:
//   Registers (critical-path dots): f, i, g gates + W_cr  -> phase-1a and
//     phase-2 weight sides run with ZERO shared-memory traffic.
//   SMEM (latency-tolerant dots):   o gate + W_hr -> their LDS cost hides
//     behind the in-flight c-exchange (phase 1b).
// x_proj inputs for step t+1 prefetched during step t.
// ----------------------------------------------------------------------------
__global__ void __launch_bounds__(NTHREADS, 1)
lstm_recur(const float* __restrict__ W_hg,   // [1024, 4096]
           const float* __restrict__ W_hr,   // [1024, 1024]
           const float* __restrict__ W_cr,   // [1024, 1024]
           const float* __restrict__ b_g,    // [4096]
           const float* __restrict__ b_r,    // [1024]
           float* __restrict__ out)          // [4096, 1024]
{
    extern __shared__ float smem[];
    float* sW1     = smem;                    // 2*8*1024 (slot0: o-gate, slot1: W_hr)
    float* scratch = smem + SW1_F;            // 8*1024
    float* sc      = smem + SW1_F + SCR_F;    // 1024
    float* sh      = sc + 1024;               // 1024

    const int tid  = threadIdx.x;
    const int w    = tid >> 5;
    const int lane = tid & 31;
    const int j0   = blockIdx.x * COLS;
    const int j    = j0 + w;

    // Per-warp pace jitter (warp-uniform) desmears poll bursts.
    const int pace = PACE_STEADY + (w << 2);   // 176..288 cyc

    // ---- Stage SMEM-resident weights (coalesced): o gate + W_hr ----
    for (int idx = tid; idx < COLS * 1024; idx += NTHREADS) {
        int cl = idx & 7;
        int k  = idx >> 3;
        sW1[(size_t)(0 * 8 + cl) * 1024 + k] = W_hg[(size_t)k * GATES + 0 * HID + j0 + cl];
        sW1[(size_t)(1 * 8 + cl) * 1024 + k] = W_hr[(size_t)k * HID + j0 + cl];
    }

    // ---- Stage register weights via scratch: f, i, g gates + W_cr ----
    // Contract: hreg[q].{x..w} = h[128q + 4*lane + d]
    float4 wf[8], wi[8], wg[8], wcr[8];
    const float4* scrv = (const float4*)scratch;
#pragma unroll
    for (int g = 0; g < 4; g++) {
        __syncthreads();
        for (int idx = tid; idx < COLS * 1024; idx += NTHREADS) {
            int cl = idx & 7;
            int k  = idx >> 3;
            float v;
            if (g == 0)      v = W_hg[(size_t)k * GATES + 1 * HID + j0 + cl];  // f
            else if (g == 1) v = W_hg[(size_t)k * GATES + 2 * HID + j0 + cl];  // i
            else if (g == 2) v = W_hg[(size_t)k * GATES + 3 * HID + j0 + cl];  // g
            else             v = W_cr[(size_t)k * HID + j0 + cl];              // W_cr
            scratch[(size_t)cl * 1024 + k] = v;
        }
        __syncthreads();
#pragma unroll
        for (int q = 0; q < 8; q++) {
            float4 v = scrv[w * 256 + 32 * q + lane];
            if (g == 0) wf[q] = v;
            else if (g == 1) wi[q] = v;
            else if (g == 2) wg[q] = v;
            else wcr[q] = v;
        }
    }
    __syncthreads();

    // Lane-0 constants
    float bg0 = 0.f, bg1 = 0.f, bg2 = 0.f, bg3 = 0.f, brj = 0.f;
    if (lane == 0) {
        bg0 = b_g[j];              // o
        bg1 = b_g[HID + j];        // f
        bg2 = b_g[2 * HID + j];    // i
        bg3 = b_g[3 * HID + j];    // g
        brj = b_r[j];
    }

    float c_state = 0.f;
    float4 hreg[8];
#pragma unroll
    for (int q = 0; q < 8; q++) hreg[q] = make_float4(0.f, 0.f, 0.f, 0.f);

    const float4* w1v = (const float4*)sW1;
    const float4* scv = (const float4*)sc;
    const float4* shv = (const float4*)sh;

    float sink = 1.5f;

    // ---- Prime x_proj pipeline for t=0 ----
    float xpo = 0.f, xpf = 0.f, xpi = 0.f, xpg = 0.f;
    if (lane == 0) {
        xpf = __ldg(g_xp + HID + j);
        xpi = __ldg(g_xp + 2 * HID + j);
        xpg = __ldg(g_xp + 3 * HID + j);
        xpo = __ldg(g_xp + j);
    }

    for (int t = 0; t < T_STEPS; t++) {
        const unsigned tagbit = (unsigned)((t + 1) & 1);

        // ---- Phase 1a (critical): f, i, g dots — pure register FMAs ----
        float af = 0.f, ai = 0.f, ag = 0.f;
#pragma unroll
        for (int q = 0; q < 8; q++) {
            float4 hv = hreg[q];
            float4 vf = wf[q], vi = wi[q], vg = wg[q];
            af += vf.x * hv.x + vf.y * hv.y + vf.z * hv.z + vf.w * hv.w;
            ai += vi.x * hv.x + vi.y * hv.y + vi.z * hv.z + vi.w * hv.w;
            ag += vg.x * hv.x + vg.y * hv.y + vg.z * hv.z + vg.w * hv.w;
        }
#pragma unroll
        for (int off = 16; off; off >>= 1) {
            af += __shfl_xor_sync(0xffffffffu, af, off);
            ai += __shfl_xor_sync(0xffffffffu, ai, off);
            ag += __shfl_xor_sync(0xffffffffu, ag, off);
        }
        if (lane == 0) {
            float f_t = fsigmoid(af + xpf + bg1);
            float i_t = fsigmoid(ai + xpi + bg2);
            c_state = f_t * c_state + i_t * ftanh(ag + xpg + bg3);
            publish(g_cpack, j, tagbit, c_state);   // barrier-1 + data, fused
        }

        // ---- Phase 1b (overlapped with c-exchange): o and W_hr from SMEM ----
        float ao = 0.f, ar = 0.f;
        const float4* wpo = w1v + (size_t)(0 * 8 + w) * 256;
        const float4* wpr = w1v + (size_t)(1 * 8 + w) * 256;
#pragma unroll
        for (int q = 0; q < 8; q++) {
            float4 hv = hreg[q];
            float4 vo = wpo[lane + 32 * q];
            ao += vo.x * hv.x + vo.y * hv.y + vo.z * hv.z + vo.w * hv.w;
            float4 vr = wpr[lane + 32 * q];
            ar += vr.x * hv.x + vr.y * hv.y + vr.z * hv.z + vr.w * hv.w;
        }
#pragma unroll
        for (int off = 16; off; off >>= 1) {
            ao += __shfl_xor_sync(0xffffffffu, ao, off);
            ar += __shfl_xor_sync(0xffffffffu, ar, off);
        }
        float o_val = 0.f, r1 = 0.f;
        if (lane == 0) {
            o_val = fsigmoid(ao + xpo + bg0);
            r1 = ar;
            // Prefetch x_proj for step t+1 (hidden behind the exchanges)
            if (t + 1 < T_STEPS) {
                const float* xpn = g_xp + (size_t)(t + 1) * GATES;
                xpf = __ldg(xpn + HID + j);
                xpi = __ldg(xpn + 2 * HID + j);
                xpg = __ldg(xpn + 3 * HID + j);
                xpo = __ldg(xpn + j);
            }
        }

        // ---- Gather c_t (grid barrier + data) ----
        poll_gather4(g_cpack, tagbit, sc, tid, pace, &sink);
        __syncthreads();

        // ---- Phase 2: r2 = c_t . W_cr[:,j] (register weights) ----
        float a2 = 0.f;
#pragma unroll
        for (int q = 0; q < 8; q++) {
            float4 cv = scv[lane + 32 * q];
            float4 wv = wcr[q];
            a2 += wv.x * cv.x + wv.y * cv.y + wv.z * cv.z + wv.w * cv.w;
        }
#pragma unroll
        for (int off = 16; off; off >>= 1)
            a2 += __shfl_xor_sync(0xffffffffu, a2, off);

        if (lane == 0) {
            float hn = o_val * ftanh(r1 + a2 + brj);
            publish(g_hpack, j, tagbit, hn);        // publish (critical)
        }

        // ---- Gather h_t; write out coalesced from gathered registers ----
        float4 hv4 = poll_gather4(g_hpack, tagbit, sh, tid, pace, &sink);
        *(float4*)(out + (size_t)t * HID + 4 * tid) = hv4;
        __syncthreads();
#pragma unroll
        for (int q = 0; q < 8; q++)
            hreg[q] = shv[lane + 32 * q];
    }

    // Prevent sink elimination (never true)
    if (sink == 12345.678f && tid == 9999) out[0] = sink;
}

// ----------------------------------------------------------------------------
// Launch
// ----------------------------------------------------------------------------
extern "C" void kernel_launch(void* const* d_in, const int* in_sizes, int n_in,
                              void* d_out, int out_size) {
    const float* x    = (const float*)d_in[0];   // [4096, 512]
    const float* W_xg = (const float*)d_in[1];   // [512, 4096]
    const float* W_hg = (const float*)d_in[2];   // [1024, 4096]
    const float* b_g  = (const float*)d_in[3];   // [1, 4096]
    const float* W_cr = (const float*)d_in[4];   // [1024, 1024]
    const float* W_hr = (const float*)d_in[5];   // [1024, 1024]
    const float* b_r  = (const float*)d_in[6];   // [1, 1024]
    float* out = (float*)d_out;                  // [4096, 1, 1024]

    (void)in_sizes; (void)n_in; (void)out_size;

    dim3 ggrid(GATES / 128, T_STEPS / 128);
    sgemm_xproj<<<ggrid, 256>>>(x, W_xg);

    cudaFuncSetAttribute(lstm_recur, cudaFuncAttributeMaxDynamicSharedMemorySize,
                         SMEM_BYTES);
    lstm_recur<<<NCTA, NTHREADS, SMEM_BYTES>>>(W_hg, W_hr, W_cr, b_g, b_r, out);
}